// round 12
// baseline (speedup 1.0000x reference)
#include <cuda_runtime.h>
#include <cuda_fp16.h>
#include <math.h>
#include <stdint.h>

// ---------------------------------------------------------------- constants
#define BROWS  131072
#define FEAT   64
#define HID    512
#define NB     10
#define PPF    29
#define PD     928
#define PDP    1024

#define BM      128
#define NT      128            // N per chunk (4 features x 32 padded params)
#define KT      64             // K per stage
#define NCHUNKS (PDP/NT)       // 8
#define KSTAGES (HID/KT)       // 8
#define G2_THREADS 128         // 4 warps, 2x2 warp grid (mt=4, p=4)

// gemm2 stage layout (bytes). Rows padded to 72 halves (144B).
#define ROWB   144
#define OFF_A  0               // A (Hh): 128 rows x 144B = 18432
#define OFF_B  18432           // B (Wh): 128 rows x 144B = 18432
#define STAGE_BYTES 36864
// Cs aliases stage buffer 1 ONLY (stage0 stays live for cross-chunk prefetch)
#define SM_CS   36864
#define CSTRIDE 133            // mod 32 = 5 (coprime) -> conflict-free spline loads
#define SMEM_TOTAL (SM_CS + BM*CSTRIDE*4)   // 104960 -> 2 CTAs/SM

// gemm1 smem
#define G1_ROWB 80
#define G1_XA   0
#define G1_W1   10240
#define G1_SMEM 51200

// ---------------------------------------------------------------- asm helpers
__device__ __forceinline__ uint32_t smem_u32(const void* p) {
    uint32_t a;
    asm("{ .reg .u64 t; cvta.to.shared.u64 t, %1; cvt.u32.u64 %0, t; }" : "=r"(a) : "l"(p));
    return a;
}
__device__ __forceinline__ void cp16(uint32_t dst, const void* src) {
    asm volatile("cp.async.cg.shared.global [%0], [%1], 16;" :: "r"(dst), "l"(src));
}
#define CP_COMMIT() asm volatile("cp.async.commit_group;" ::: "memory")
#define CP_WAIT(n)  asm volatile("cp.async.wait_group %0;" :: "n"(n) : "memory")

#define LDSM_X4(r, addr) \
    asm volatile("ldmatrix.sync.aligned.m8n8.x4.shared.b16 {%0,%1,%2,%3}, [%4];" \
        : "=r"((r)[0]), "=r"((r)[1]), "=r"((r)[2]), "=r"((r)[3]) : "r"(addr))

#define MMA16816(d, a, b) \
    asm volatile("mma.sync.aligned.m16n8k16.row.col.f32.f16.f16.f32 " \
        "{%0,%1,%2,%3},{%4,%5,%6,%7},{%8,%9},{%0,%1,%2,%3};" \
        : "+f"((d)[0]), "+f"((d)[1]), "+f"((d)[2]), "+f"((d)[3]) \
        : "r"((a)[0]), "r"((a)[1]), "r"((a)[2]), "r"((a)[3]), "r"((b)[0]), "r"((b)[1]))

// ---------------------------------------------------------------- scratch
__device__ __half g_Hh[(size_t)BROWS * HID];   // 134 MB
__device__ __half g_WhT[PDP * HID];            // W2^T padded [n][k], 1 MB
__device__ __half g_W1T[HID * 32];             // W1^T [n=512][k=32]
__device__ float  g_b2p[PDP];

// ---------------------------------------------------------------- prep
__global__ void prep_kernel(const float* __restrict__ W2, const float* __restrict__ b2,
                            const float* __restrict__ W1) {
    int idx = blockIdx.x * blockDim.x + threadIdx.x;
    if (idx < PDP * HID) {
        int n = idx >> 9;
        int k = idx & 511;
        int f = n >> 5, p = n & 31;
        float w = (p < PPF) ? W2[k * PD + f * PPF + p] : 0.0f;
        g_WhT[idx] = __float2half_rn(w);
    }
    if (idx < HID * 32) {
        int n = idx >> 5, k = idx & 31;
        g_W1T[idx] = __float2half_rn(W1[k * HID + n]);
    }
    if (idx < PDP) {
        int f = idx >> 5, p = idx & 31;
        g_b2p[idx] = (p < PPF) ? b2[f * PPF + p] : 0.0f;
    }
}

// ---------------------------------------------------------------- stage 1: H = relu(id@W1+b1) via HMMA
__global__ __launch_bounds__(256) void gemm1_kernel(
    const float* __restrict__ x, const float* __restrict__ b1)
{
    extern __shared__ char smem[];
    uint32_t sb = smem_u32(smem);
    int tid = threadIdx.x;
    int wid = tid >> 5, lane = tid & 31;
    size_t rb = (size_t)blockIdx.x * BM;

#pragma unroll
    for (int j = 0; j < 8; j++) {
        int idx = tid + 256 * j;
        int row = idx >> 4, c = idx & 15;
        float4 v = __ldg((const float4*)x + (rb + row) * 16 + c);
        __half2 h2 = __floats2half2_rn(v.y, v.w);
        *(__half2*)(smem + G1_XA + row * G1_ROWB + c * 4) = h2;
    }
#pragma unroll
    for (int j = 0; j < 8; j++) {
        int idx = tid + 256 * j;
        int row = idx >> 2, q = idx & 3;
        *(float4*)(smem + G1_W1 + row * G1_ROWB + q * 16) =
            ((const float4*)(g_W1T + row * 32))[q];
    }
    __syncthreads();

    int warpRow = (wid & 3) * 32;
    int warpCol = (wid >> 2) * 64;
    int aRow = (lane & 15);
    int aKof = (lane >> 4) * 8;
    int bN   = (lane & 7) + ((lane >> 4) << 3);
    int bKof = ((lane >> 3) & 1) * 8;

    uint32_t ah[2][2][4];
#pragma unroll
    for (int k16 = 0; k16 < 2; k16++)
#pragma unroll
        for (int mt = 0; mt < 2; mt++) {
            uint32_t aoff = (uint32_t)((warpRow + mt * 16 + aRow) * G1_ROWB + (k16 * 16 + aKof) * 2);
            LDSM_X4(ah[k16][mt], sb + G1_XA + aoff);
        }

#pragma unroll
    for (int ch = 0; ch < 4; ch++) {
        float acc[2][8][4];
#pragma unroll
        for (int mt = 0; mt < 2; mt++)
#pragma unroll
            for (int nt = 0; nt < 8; nt++)
#pragma unroll
                for (int r = 0; r < 4; r++) acc[mt][nt][r] = 0.0f;

#pragma unroll
        for (int k16 = 0; k16 < 2; k16++) {
#pragma unroll
            for (int p = 0; p < 4; p++) {
                uint32_t boff = (uint32_t)((ch * 128 + warpCol + p * 16 + bN) * G1_ROWB + (k16 * 16 + bKof) * 2);
                uint32_t bh[4];
                LDSM_X4(bh, sb + G1_W1 + boff);
#pragma unroll
                for (int mt = 0; mt < 2; mt++) {
                    MMA16816(acc[mt][2 * p],     ah[k16][mt], bh);
                    MMA16816(acc[mt][2 * p + 1], ah[k16][mt], bh + 2);
                }
            }
        }

#pragma unroll
        for (int mt = 0; mt < 2; mt++) {
#pragma unroll
            for (int nt = 0; nt < 8; nt++) {
                int r = warpRow + mt * 16 + (lane >> 2);
                int c = ch * 128 + warpCol + nt * 8 + (lane & 3) * 2;
                float2 bb = *(const float2*)(b1 + c);
                __half2 h0 = __floats2half2_rn(fmaxf(acc[mt][nt][0] + bb.x, 0.f),
                                               fmaxf(acc[mt][nt][1] + bb.y, 0.f));
                __half2 h1 = __floats2half2_rn(fmaxf(acc[mt][nt][2] + bb.x, 0.f),
                                               fmaxf(acc[mt][nt][3] + bb.y, 0.f));
                *(__half2*)(g_Hh + (rb + r) * HID + c)     = h0;
                *(__half2*)(g_Hh + (rb + r + 8) * HID + c) = h1;
            }
        }
    }
}

// ---------------------------------------------------------------- spline
__device__ __forceinline__ float expp(float x) {
    // deg-5 Taylor; |x| <= ~0.5 for softmax logits -> err <= 2e-5 rel
    float r = 8.333333333e-3f;           // 1/120
    r = r * x + 4.166666667e-2f;         // 1/24
    r = r * x + 1.666666667e-1f;         // 1/6
    r = r * x + 0.5f;
    r = r * x + 1.0f;
    r = r * x + 1.0f;
    return r;
}
__device__ __forceinline__ float softplusf_fast(float v) {
    return fmaxf(v, 0.0f) + __logf(1.0f + __expf(-fabsf(v)));
}

__device__ __forceinline__ void rqs_spline(float xv, const float* __restrict__ p,
                                           float& y_out, float& lad_out)
{
    const float S = 0.044194173824159216f;  // 1/sqrt(512)
    bool inside = (xv >= -1.0f) && (xv <= 1.0f);
    float xc = fminf(fmaxf(xv, -1.0f), 1.0f);

    float vw[10], vh[10];
    float sw = 0.0f, sh = 0.0f;
#pragma unroll
    for (int i = 0; i < 10; i++) {
        vw[i] = expp(p[i] * S);
        vh[i] = expp(p[10 + i] * S);
        sw += vw[i];
        sh += vh[i];
    }
    float rw = __fdividef(0.99f, sw), rh = __fdividef(0.99f, sh);

    float cumw = 0.0f, cumh = 0.0f;
    float Lw = -1.0f, Lh = -1.0f;
    float icw = -1.0f, iw = 1.0f, ich = -1.0f, ih = 1.0f;
    int isel = 0;
#pragma unroll
    for (int i = 0; i < 10; i++) {
        cumw += 0.001f + vw[i] * rw;
        cumh += 0.001f + vh[i] * rh;
        float Rw = (i == 9) ? 1.0f : (2.0f * cumw - 1.0f);
        float Rh = (i == 9) ? 1.0f : (2.0f * cumh - 1.0f);
        if (xc >= Lw) {
            icw = Lw; iw = Rw - Lw;
            ich = Lh; ih = Rh - Lh;
            isel = i;
        }
        Lw = Rw; Lh = Rh;
    }
    float dk  = (isel > 0) ? (0.001f + softplusf_fast(p[19 + isel])) : 1.0f;
    float dk1 = (isel < 9) ? (0.001f + softplusf_fast(p[20 + isel])) : 1.0f;

    float riw = __fdividef(1.0f, iw);
    float theta = (xc - icw) * riw;
    float om = 1.0f - theta;
    float t1m = theta * om;
    float delta = ih * riw;
    float numer = ih * (delta * theta * theta + dk * t1m);
    float denom = delta + (dk + dk1 - 2.0f * delta) * t1m;
    float rden = __fdividef(1.0f, denom);
    float yv = ich + numer * rden;
    float dnum = delta * delta * (dk1 * theta * theta + 2.0f * delta * t1m + dk * om * om);
    float l = __logf(dnum * rden * rden);

    y_out = inside ? yv : xv;
    lad_out = inside ? l : 0.0f;
}

// ---------------------------------------------------------------- stage 2: HMMA GEMM + fused spline
// 128 threads, 2x2 warp grid, mt=4 p=4 (128x128 tile), 2 CTAs/SM
__device__ __forceinline__ void load_stage(uint32_t sb, int buf, int kt, int nc,
                                           size_t rb, int tid)
{
    uint32_t base = sb + buf * STAGE_BYTES;
#pragma unroll
    for (int j = 0; j < 16; j++) {
        int id = tid + G2_THREADS * j;   // 0..2047
        if (id < 1024) {
            int row = id >> 3, q = id & 7;
            cp16(base + OFF_A + row * ROWB + q * 16,
                 g_Hh + (rb + row) * HID + kt * KT + q * 8);
        } else {
            int v = id - 1024;
            int row = v >> 3, q = v & 7;
            cp16(base + OFF_B + row * ROWB + q * 16,
                 g_WhT + (size_t)(nc * NT + row) * HID + kt * KT + q * 8);
        }
    }
    CP_COMMIT();
}

__global__ __launch_bounds__(G2_THREADS, 2) void gemm2_mma_kernel(
    const float* __restrict__ x, float* __restrict__ out,
    float* __restrict__ lad_out, float* __restrict__ ot_out)
{
    extern __shared__ char smem[];
    uint32_t sb = smem_u32(smem);
    int tid = threadIdx.x;
    int wid = tid >> 5, lane = tid & 31;
    size_t rb = (size_t)blockIdx.x * BM;

    int warpRow = (wid & 1) * 64;        // 2 warp-rows of 64 (mt=4)
    int warpCol = (wid >> 1) * 64;       // 2 warp-cols of 64 (p=4)

    float* Cs = (float*)(smem + SM_CS);

    int aRow = (lane & 15);
    int aKof = (lane >> 4) * 8;
    int bN   = (lane & 7) + ((lane >> 4) << 3);
    int bKof = ((lane >> 3) & 1) * 8;

    float lad_acc = 0.0f, ot_acc = 0.0f;

    // prefetch chunk 0 stage 0 into buf0
    load_stage(sb, 0, 0, 0, rb, tid);

#pragma unroll 1
    for (int nc = 0; nc < NCHUNKS; nc++) {
        float acc[4][8][4];
#pragma unroll
        for (int mt = 0; mt < 4; mt++)
#pragma unroll
            for (int nt = 0; nt < 8; nt++)
#pragma unroll
                for (int r = 0; r < 4; r++) acc[mt][nt][r] = 0.0f;

        // single-sync double-buffered pipeline (see R11 derivation)
#pragma unroll 1
        for (int kt = 0; kt < KSTAGES; kt++) {
            int buf = kt & 1;
            CP_WAIT(0);
            __syncthreads();
            if (kt + 1 < KSTAGES)
                load_stage(sb, buf ^ 1, kt + 1, nc, rb, tid);
            else if (nc + 1 < NCHUNKS)
                load_stage(sb, 0, 0, nc + 1, rb, tid);   // next chunk prefetch -> buf0

            uint32_t base = sb + buf * STAGE_BYTES;
#pragma unroll
            for (int k16 = 0; k16 < 4; k16++) {
                int ko = k16 * 16;
                uint32_t ah[4][4];
#pragma unroll
                for (int mt = 0; mt < 4; mt++) {
                    uint32_t aoff = (uint32_t)((warpRow + mt * 16 + aRow) * ROWB + (ko + aKof) * 2);
                    LDSM_X4(ah[mt], base + OFF_A + aoff);
                }
#pragma unroll
                for (int p = 0; p < 4; p++) {
                    uint32_t boff = (uint32_t)((warpCol + p * 16 + bN) * ROWB + (ko + bKof) * 2);
                    uint32_t bh[4];
                    LDSM_X4(bh, base + OFF_B + boff);
#pragma unroll
                    for (int mt = 0; mt < 4; mt++) {
                        MMA16816(acc[mt][2 * p],     ah[mt], bh);
                        MMA16816(acc[mt][2 * p + 1], ah[mt], bh + 2);
                    }
                }
            }
        }
        __syncthreads();   // all warps done reading buf1 before dump overwrites it

        // ---- dump accumulators (+ bias fold) into Cs (scalar: CSTRIDE odd) ----
#pragma unroll
        for (int nt = 0; nt < 8; nt++) {
            int c = warpCol + nt * 8 + (lane & 3) * 2;
            float2 bb = __ldg((const float2*)(g_b2p + nc * NT + c));
#pragma unroll
            for (int mt = 0; mt < 4; mt++) {
                int r = warpRow + mt * 16 + (lane >> 2);
                Cs[r * CSTRIDE + c]           = acc[mt][nt][0] + bb.x;
                Cs[r * CSTRIDE + c + 1]       = acc[mt][nt][1] + bb.y;
                Cs[(r + 8) * CSTRIDE + c]     = acc[mt][nt][2] + bb.x;
                Cs[(r + 8) * CSTRIDE + c + 1] = acc[mt][nt][3] + bb.y;
            }
        }
        __syncthreads();

        // ---- spline: thread tid owns row tid; 4 features per chunk ----
        {
            const float* rowC = Cs + tid * CSTRIDE;
#pragma unroll 1
            for (int t = 0; t < 4; t++) {
                int fg = nc * 4 + t;
                float2 xp = *(const float2*)(x + (rb + tid) * FEAT + 2 * fg);
                float y, lad;
                rqs_spline(xp.x, rowC + t * 32, y, lad);
                *(float2*)(out + (rb + tid) * FEAT + 2 * fg) = make_float2(y, xp.y);
                lad_acc += lad;
                float d = xp.x - y;
                ot_acc += d * d;
            }
        }
        // no post-spline sync: next chunk's kt=0 barrier orders spline reads
        // before the kt=1 load overwrites Cs (=buf1)
    }

    // each thread owns its full row: direct global write, no reduction
    lad_out[rb + tid] = lad_acc;
    ot_out[rb + tid]  = ot_acc;
}

// ---------------------------------------------------------------- launcher
extern "C" void kernel_launch(void* const* d_in, const int* in_sizes, int n_in,
                              void* d_out, int out_size)
{
    const float* x  = (const float*)d_in[0];
    const float* W1 = (const float*)d_in[1];
    const float* b1 = (const float*)d_in[2];
    const float* W2 = (const float*)d_in[3];
    const float* b2 = (const float*)d_in[4];

    float* out = (float*)d_out;
    float* lad = out + (size_t)BROWS * FEAT;
    float* ot  = lad + BROWS;

    cudaFuncSetAttribute(gemm1_kernel, cudaFuncAttributeMaxDynamicSharedMemorySize, G1_SMEM);
    cudaFuncSetAttribute(gemm2_mma_kernel, cudaFuncAttributeMaxDynamicSharedMemorySize, SMEM_TOTAL);

    prep_kernel<<<(PDP * HID + 255) / 256, 256>>>(W2, b2, W1);
    gemm1_kernel<<<BROWS / BM, 256, G1_SMEM>>>(x, b1);
    gemm2_mma_kernel<<<BROWS / BM, G2_THREADS, SMEM_TOTAL>>>(x, out, lad, ot);
}

// round 13
// speedup vs baseline: 1.0480x; 1.0480x over previous
#include <cuda_runtime.h>
#include <cuda_fp16.h>
#include <math.h>
#include <stdint.h>

// ---------------------------------------------------------------- constants
#define BROWS  131072
#define FEAT   64
#define HID    512
#define NB     10
#define PPF    29
#define PD     928
#define PDP    1024

#define BM      128
#define NT      128            // N per chunk (4 features x 32 padded params)
#define KT      64             // K per stage
#define NCHUNKS (PDP/NT)       // 8
#define KSTAGES (HID/KT)       // 8

// gemm2 stage layout (bytes). Rows padded to 72 halves (144B).
#define ROWB   144
#define OFF_A  0               // A (Hh): 128 rows x 144B = 18432
#define OFF_B  18432           // B (Wh): 128 rows x 144B = 18432
#define STAGE_BYTES 36864
// Cs aliases stage buffer 1 ONLY (stage0 stays live for cross-chunk prefetch)
#define SM_CS   36864
#define CSTRIDE 133            // mod 32 = 5 (coprime) -> conflict-free spline loads
#define SM_LAD  (SM_CS + BM*CSTRIDE*4)   // 36864+68096 = 104960
#define SM_OT   (SM_LAD + BM*4)
#define SMEM_TOTAL (SM_OT + BM*4)        // 105984 -> 2 CTAs/SM

// gemm1 smem
#define G1_ROWB 80
#define G1_XA   0
#define G1_W1   10240
#define G1_SMEM 51200

// ---------------------------------------------------------------- asm helpers
__device__ __forceinline__ uint32_t smem_u32(const void* p) {
    uint32_t a;
    asm("{ .reg .u64 t; cvta.to.shared.u64 t, %1; cvt.u32.u64 %0, t; }" : "=r"(a) : "l"(p));
    return a;
}
__device__ __forceinline__ void cp16(uint32_t dst, const void* src) {
    asm volatile("cp.async.cg.shared.global [%0], [%1], 16;" :: "r"(dst), "l"(src));
}
#define CP_COMMIT() asm volatile("cp.async.commit_group;" ::: "memory")
#define CP_WAIT(n)  asm volatile("cp.async.wait_group %0;" :: "n"(n) : "memory")

#define LDSM_X4(r, addr) \
    asm volatile("ldmatrix.sync.aligned.m8n8.x4.shared.b16 {%0,%1,%2,%3}, [%4];" \
        : "=r"((r)[0]), "=r"((r)[1]), "=r"((r)[2]), "=r"((r)[3]) : "r"(addr))

#define MMA16816(d, a, b) \
    asm volatile("mma.sync.aligned.m16n8k16.row.col.f32.f16.f16.f32 " \
        "{%0,%1,%2,%3},{%4,%5,%6,%7},{%8,%9},{%0,%1,%2,%3};" \
        : "+f"((d)[0]), "+f"((d)[1]), "+f"((d)[2]), "+f"((d)[3]) \
        : "r"((a)[0]), "r"((a)[1]), "r"((a)[2]), "r"((a)[3]), "r"((b)[0]), "r"((b)[1]))

// ---------------------------------------------------------------- scratch
__device__ __half g_Hh[(size_t)BROWS * HID];   // 134 MB
__device__ __half g_WhT[PDP * HID];            // W2^T padded [n][k], 1 MB
__device__ __half g_W1T[HID * 32];             // W1^T [n=512][k=32]
__device__ float  g_b2p[PDP];

// ---------------------------------------------------------------- prep
__global__ void prep_kernel(const float* __restrict__ W2, const float* __restrict__ b2,
                            const float* __restrict__ W1) {
    int idx = blockIdx.x * blockDim.x + threadIdx.x;
    if (idx < PDP * HID) {
        int n = idx >> 9;
        int k = idx & 511;
        int f = n >> 5, p = n & 31;
        float w = (p < PPF) ? W2[k * PD + f * PPF + p] : 0.0f;
        g_WhT[idx] = __float2half_rn(w);
    }
    if (idx < HID * 32) {
        int n = idx >> 5, k = idx & 31;
        g_W1T[idx] = __float2half_rn(W1[k * HID + n]);
    }
    if (idx < PDP) {
        int f = idx >> 5, p = idx & 31;
        g_b2p[idx] = (p < PPF) ? b2[f * PPF + p] : 0.0f;
    }
}

// ---------------------------------------------------------------- stage 1: H = relu(id@W1+b1) via HMMA
__global__ __launch_bounds__(256) void gemm1_kernel(
    const float* __restrict__ x, const float* __restrict__ b1)
{
    extern __shared__ char smem[];
    uint32_t sb = smem_u32(smem);
    int tid = threadIdx.x;
    int wid = tid >> 5, lane = tid & 31;
    size_t rb = (size_t)blockIdx.x * BM;

#pragma unroll
    for (int j = 0; j < 8; j++) {
        int idx = tid + 256 * j;
        int row = idx >> 4, c = idx & 15;
        float4 v = __ldg((const float4*)x + (rb + row) * 16 + c);
        __half2 h2 = __floats2half2_rn(v.y, v.w);
        *(__half2*)(smem + G1_XA + row * G1_ROWB + c * 4) = h2;
    }
#pragma unroll
    for (int j = 0; j < 8; j++) {
        int idx = tid + 256 * j;
        int row = idx >> 2, q = idx & 3;
        *(float4*)(smem + G1_W1 + row * G1_ROWB + q * 16) =
            ((const float4*)(g_W1T + row * 32))[q];
    }
    __syncthreads();

    int warpRow = (wid & 3) * 32;
    int warpCol = (wid >> 2) * 64;
    int aRow = (lane & 15);
    int aKof = (lane >> 4) * 8;
    int bN   = (lane & 7) + ((lane >> 4) << 3);
    int bKof = ((lane >> 3) & 1) * 8;

    uint32_t ah[2][2][4];
#pragma unroll
    for (int k16 = 0; k16 < 2; k16++)
#pragma unroll
        for (int mt = 0; mt < 2; mt++) {
            uint32_t aoff = (uint32_t)((warpRow + mt * 16 + aRow) * G1_ROWB + (k16 * 16 + aKof) * 2);
            LDSM_X4(ah[k16][mt], sb + G1_XA + aoff);
        }

#pragma unroll
    for (int ch = 0; ch < 4; ch++) {
        float acc[2][8][4];
#pragma unroll
        for (int mt = 0; mt < 2; mt++)
#pragma unroll
            for (int nt = 0; nt < 8; nt++)
#pragma unroll
                for (int r = 0; r < 4; r++) acc[mt][nt][r] = 0.0f;

#pragma unroll
        for (int k16 = 0; k16 < 2; k16++) {
#pragma unroll
            for (int p = 0; p < 4; p++) {
                uint32_t boff = (uint32_t)((ch * 128 + warpCol + p * 16 + bN) * G1_ROWB + (k16 * 16 + bKof) * 2);
                uint32_t bh[4];
                LDSM_X4(bh, sb + G1_W1 + boff);
#pragma unroll
                for (int mt = 0; mt < 2; mt++) {
                    MMA16816(acc[mt][2 * p],     ah[k16][mt], bh);
                    MMA16816(acc[mt][2 * p + 1], ah[k16][mt], bh + 2);
                }
            }
        }

#pragma unroll
        for (int mt = 0; mt < 2; mt++) {
#pragma unroll
            for (int nt = 0; nt < 8; nt++) {
                int r = warpRow + mt * 16 + (lane >> 2);
                int c = ch * 128 + warpCol + nt * 8 + (lane & 3) * 2;
                float2 bb = *(const float2*)(b1 + c);
                __half2 h0 = __floats2half2_rn(fmaxf(acc[mt][nt][0] + bb.x, 0.f),
                                               fmaxf(acc[mt][nt][1] + bb.y, 0.f));
                __half2 h1 = __floats2half2_rn(fmaxf(acc[mt][nt][2] + bb.x, 0.f),
                                               fmaxf(acc[mt][nt][3] + bb.y, 0.f));
                *(__half2*)(g_Hh + (rb + r) * HID + c)     = h0;
                *(__half2*)(g_Hh + (rb + r + 8) * HID + c) = h1;
            }
        }
    }
}

// ---------------------------------------------------------------- spline
__device__ __forceinline__ float expp(float x) {
    // deg-5 Taylor; |x| <= ~0.5 for softmax logits -> err <= 2e-5 rel
    float r = 8.333333333e-3f;           // 1/120
    r = r * x + 4.166666667e-2f;         // 1/24
    r = r * x + 1.666666667e-1f;         // 1/6
    r = r * x + 0.5f;
    r = r * x + 1.0f;
    r = r * x + 1.0f;
    return r;
}
__device__ __forceinline__ float softplusf_fast(float v) {
    return fmaxf(v, 0.0f) + __logf(1.0f + __expf(-fabsf(v)));
}

__device__ __forceinline__ void rqs_spline(float xv, const float* __restrict__ p,
                                           float& y_out, float& lad_out)
{
    const float S = 0.044194173824159216f;  // 1/sqrt(512)
    bool inside = (xv >= -1.0f) && (xv <= 1.0f);
    float xc = fminf(fmaxf(xv, -1.0f), 1.0f);

    float vw[10], vh[10];
    float sw = 0.0f, sh = 0.0f;
#pragma unroll
    for (int i = 0; i < 10; i++) {
        vw[i] = expp(p[i] * S);
        vh[i] = expp(p[10 + i] * S);
        sw += vw[i];
        sh += vh[i];
    }
    float rw = __fdividef(0.99f, sw), rh = __fdividef(0.99f, sh);

    float cumw = 0.0f, cumh = 0.0f;
    float Lw = -1.0f, Lh = -1.0f;
    float icw = -1.0f, iw = 1.0f, ich = -1.0f, ih = 1.0f;
    int isel = 0;
#pragma unroll
    for (int i = 0; i < 10; i++) {
        cumw += 0.001f + vw[i] * rw;
        cumh += 0.001f + vh[i] * rh;
        float Rw = (i == 9) ? 1.0f : (2.0f * cumw - 1.0f);
        float Rh = (i == 9) ? 1.0f : (2.0f * cumh - 1.0f);
        if (xc >= Lw) {
            icw = Lw; iw = Rw - Lw;
            ich = Lh; ih = Rh - Lh;
            isel = i;
        }
        Lw = Rw; Lh = Rh;
    }
    float dk  = (isel > 0) ? (0.001f + softplusf_fast(p[19 + isel])) : 1.0f;
    float dk1 = (isel < 9) ? (0.001f + softplusf_fast(p[20 + isel])) : 1.0f;

    float riw = __fdividef(1.0f, iw);
    float theta = (xc - icw) * riw;
    float om = 1.0f - theta;
    float t1m = theta * om;
    float delta = ih * riw;
    float numer = ih * (delta * theta * theta + dk * t1m);
    float denom = delta + (dk + dk1 - 2.0f * delta) * t1m;
    float rden = __fdividef(1.0f, denom);
    float yv = ich + numer * rden;
    float dnum = delta * delta * (dk1 * theta * theta + 2.0f * delta * t1m + dk * om * om);
    float l = __logf(dnum * rden * rden);

    y_out = inside ? yv : xv;
    lad_out = inside ? l : 0.0f;
}

// ---------------------------------------------------------------- stage 2: HMMA GEMM + fused spline
// (R11 config: 256 threads, 4x2 warp grid, 2 CTAs/SM — 16 warps/SM is required;
//  R12's 4-warp variant starved the SMSPs and regressed)
__device__ __forceinline__ void load_stage(uint32_t sb, int buf, int kt, int nc,
                                           size_t rb, int tid)
{
    uint32_t base = sb + buf * STAGE_BYTES;
#pragma unroll
    for (int j = 0; j < 8; j++) {
        int id = tid + 256 * j;   // 0..2047
        if (id < 1024) {
            int row = id >> 3, q = id & 7;
            cp16(base + OFF_A + row * ROWB + q * 16,
                 g_Hh + (rb + row) * HID + kt * KT + q * 8);
        } else {
            int v = id - 1024;
            int row = v >> 3, q = v & 7;
            cp16(base + OFF_B + row * ROWB + q * 16,
                 g_WhT + (size_t)(nc * NT + row) * HID + kt * KT + q * 8);
        }
    }
    CP_COMMIT();
}

__global__ __launch_bounds__(256, 2) void gemm2_mma_kernel(
    const float* __restrict__ x, float* __restrict__ out,
    float* __restrict__ lad_out, float* __restrict__ ot_out)
{
    extern __shared__ char smem[];
    uint32_t sb = smem_u32(smem);
    int tid = threadIdx.x;
    int wid = tid >> 5, lane = tid & 31;
    size_t rb = (size_t)blockIdx.x * BM;

    int warpRow = (wid & 3) * 32;        // 4 warp-rows of 32
    int warpCol = (wid >> 2) * 64;       // 2 warp-cols of 64

    float* Cs   = (float*)(smem + SM_CS);
    float* ladR = (float*)(smem + SM_LAD);
    float* otR  = (float*)(smem + SM_OT);

    int aRow = (lane & 15);
    int aKof = (lane >> 4) * 8;
    int bN   = (lane & 7) + ((lane >> 4) << 3);
    int bKof = ((lane >> 3) & 1) * 8;

    float lad_acc = 0.0f, ot_acc = 0.0f;
    int srow = tid & 127;

    // prefetch chunk 0 stage 0 into buf0
    load_stage(sb, 0, 0, 0, rb, tid);

#pragma unroll 1
    for (int nc = 0; nc < NCHUNKS; nc++) {
        float acc[2][8][4];
#pragma unroll
        for (int mt = 0; mt < 2; mt++)
#pragma unroll
            for (int nt = 0; nt < 8; nt++)
#pragma unroll
                for (int r = 0; r < 4; r++) acc[mt][nt][r] = 0.0f;

        // single-sync double-buffered pipeline (see R11 derivation)
#pragma unroll 1
        for (int kt = 0; kt < KSTAGES; kt++) {
            int buf = kt & 1;
            CP_WAIT(0);
            __syncthreads();
            if (kt + 1 < KSTAGES)
                load_stage(sb, buf ^ 1, kt + 1, nc, rb, tid);
            else if (nc + 1 < NCHUNKS)
                load_stage(sb, 0, 0, nc + 1, rb, tid);   // next chunk prefetch -> buf0

            uint32_t base = sb + buf * STAGE_BYTES;
#pragma unroll
            for (int k16 = 0; k16 < 4; k16++) {
                int ko = k16 * 16;
                uint32_t ah[2][4];
#pragma unroll
                for (int mt = 0; mt < 2; mt++) {
                    uint32_t aoff = (uint32_t)((warpRow + mt * 16 + aRow) * ROWB + (ko + aKof) * 2);
                    LDSM_X4(ah[mt], base + OFF_A + aoff);
                }
#pragma unroll
                for (int p = 0; p < 4; p++) {
                    uint32_t boff = (uint32_t)((warpCol + p * 16 + bN) * ROWB + (ko + bKof) * 2);
                    uint32_t bh[4];
                    LDSM_X4(bh, base + OFF_B + boff);
#pragma unroll
                    for (int mt = 0; mt < 2; mt++) {
                        MMA16816(acc[mt][2 * p],     ah[mt], bh);
                        MMA16816(acc[mt][2 * p + 1], ah[mt], bh + 2);
                    }
                }
            }
        }
        __syncthreads();   // all warps done reading buf1 before dump overwrites it

        // ---- dump accumulators (+ bias fold) into Cs (scalar: CSTRIDE odd) ----
#pragma unroll
        for (int nt = 0; nt < 8; nt++) {
            int c = warpCol + nt * 8 + (lane & 3) * 2;
            float2 bb = __ldg((const float2*)(g_b2p + nc * NT + c));
#pragma unroll
            for (int mt = 0; mt < 2; mt++) {
                int r = warpRow + mt * 16 + (lane >> 2);
                Cs[r * CSTRIDE + c]           = acc[mt][nt][0] + bb.x;
                Cs[r * CSTRIDE + c + 1]       = acc[mt][nt][1] + bb.y;
                Cs[(r + 8) * CSTRIDE + c]     = acc[mt][nt][2] + bb.x;
                Cs[(r + 8) * CSTRIDE + c + 1] = acc[mt][nt][3] + bb.y;
            }
        }
        __syncthreads();

        // ---- spline: 512 tasks, 2/thread, fully unrolled so the two
        //      latency-bound spline chains interleave (ILP) ----
#pragma unroll
        for (int t = 0; t < 2; t++) {
            int task = tid + 256 * t;
            int row = task & 127;
            int fl  = task >> 7;          // t=0 -> 0/1, t=1 -> 2/3
            int fg  = nc * 4 + fl;
            const float* bp = Cs + row * CSTRIDE + fl * 32;
            float2 xp = *(const float2*)(x + (rb + row) * FEAT + 2 * fg);
            float y, lad;
            rqs_spline(xp.x, bp, y, lad);
            *(float2*)(out + (rb + row) * FEAT + 2 * fg) = make_float2(y, xp.y);
            lad_acc += lad;
            float d = xp.x - y;
            ot_acc += d * d;
        }
        // no post-spline sync: next chunk's kt=0 barrier orders spline reads
        // before the kt=1 load overwrites Cs (=buf1)
    }

    // ---- per-row reductions (rows covered by tid and tid+128) ----
    __syncthreads();
    if (tid < 128) { ladR[srow] = lad_acc; otR[srow] = ot_acc; }
    __syncthreads();
    if (tid >= 128) { ladR[srow] += lad_acc; otR[srow] += ot_acc; }
    __syncthreads();

    if (tid < BM) {
        lad_out[rb + tid] = ladR[tid];
        ot_out[rb + tid]  = otR[tid];
    }
}

// ---------------------------------------------------------------- launcher
extern "C" void kernel_launch(void* const* d_in, const int* in_sizes, int n_in,
                              void* d_out, int out_size)
{
    const float* x  = (const float*)d_in[0];
    const float* W1 = (const float*)d_in[1];
    const float* b1 = (const float*)d_in[2];
    const float* W2 = (const float*)d_in[3];
    const float* b2 = (const float*)d_in[4];

    float* out = (float*)d_out;
    float* lad = out + (size_t)BROWS * FEAT;
    float* ot  = lad + BROWS;

    cudaFuncSetAttribute(gemm1_kernel, cudaFuncAttributeMaxDynamicSharedMemorySize, G1_SMEM);
    cudaFuncSetAttribute(gemm2_mma_kernel, cudaFuncAttributeMaxDynamicSharedMemorySize, SMEM_TOTAL);

    prep_kernel<<<(PDP * HID + 255) / 256, 256>>>(W2, b2, W1);
    gemm1_kernel<<<BROWS / BM, 256, G1_SMEM>>>(x, b1);
    gemm2_mma_kernel<<<BROWS / BM, 256, SMEM_TOTAL>>>(x, out, lad, ot);
}

// round 14
// speedup vs baseline: 1.1723x; 1.1186x over previous
#include <cuda_runtime.h>
#include <cuda_fp16.h>
#include <math.h>
#include <stdint.h>

// ---------------------------------------------------------------- constants
#define BROWS  131072
#define FEAT   64
#define HID    512
#define NB     10
#define PPF    29
#define PD     928
#define PDP    1024

#define BM      128
#define NT      128            // N per chunk (4 features x 32 padded params)
#define KT      64             // K per stage
#define NCHUNKS (PDP/NT)       // 8
#define KSTAGES (HID/KT)       // 8
#define NBLKS   (BROWS/BM)     // 1024

// stage tile: 128 rows x 72 halves (144B, padding baked into GMEM layout)
#define ROWB   144
#define TILE_HALVES (128*72)       // 9216
#define TILE_BYTES  (128*ROWB)     // 18432
#define OFF_A  0
#define OFF_B  18432
#define STAGE_BYTES 36864
// Cs aliases stage buffer 1 ONLY (stage0 stays live for cross-chunk prefetch)
#define SM_CS   36864
#define CSTRIDE 133            // mod 32 = 5 (coprime) -> conflict-free spline loads
#define SM_LAD  (SM_CS + BM*CSTRIDE*4)   // 104960
#define SM_OT   (SM_LAD + BM*4)
#define SM_MBAR (SM_OT + BM*4)           // 105984 (two 8B mbarriers)
#define SMEM_TOTAL (SM_MBAR + 16)        // 106000 -> 2 CTAs/SM

// gemm1 smem
#define G1_ROWB 80
#define G1_XA   0
#define G1_W1   10240
#define G1_SMEM 51200

// ---------------------------------------------------------------- asm helpers
__device__ __forceinline__ uint32_t smem_u32(const void* p) {
    uint32_t a;
    asm("{ .reg .u64 t; cvta.to.shared.u64 t, %1; cvt.u32.u64 %0, t; }" : "=r"(a) : "l"(p));
    return a;
}
#define MBARRIER_INIT(addr, cnt) \
    asm volatile("mbarrier.init.shared.b64 [%0], %1;" :: "r"(addr), "r"(cnt) : "memory")
#define MBARRIER_EXPECT_TX(addr, bytes) \
    asm volatile("mbarrier.arrive.expect_tx.shared.b64 _, [%0], %1;" :: "r"(addr), "r"(bytes) : "memory")
#define MBARRIER_WAIT_PARITY(addr, par) do { \
    uint32_t _m = (addr), _p = (par), _d; \
    asm volatile("{ .reg .pred p; mbarrier.try_wait.parity.acquire.cta.shared::cta.b64 p, [%1], %2; selp.b32 %0,1,0,p; }" \
        : "=r"(_d) : "r"(_m), "r"(_p) : "memory"); \
    if (!_d) { \
        asm volatile("{ .reg .pred P1;\nWL_%=:\nmbarrier.try_wait.parity.acquire.cta.shared::cta.b64 P1, [%0], %1, 0x989680;\n@P1 bra.uni WD_%=;\nbra.uni WL_%=;\nWD_%=:\n}" \
            :: "r"(_m), "r"(_p) : "memory"); \
    } } while (0)
#define BULK_LD(dst, src, sz, mb) \
    asm volatile("cp.async.bulk.shared::cluster.global.mbarrier::complete_tx::bytes [%0], [%1], %2, [%3];" \
        :: "r"(dst), "l"(src), "r"(sz), "r"(mb) : "memory")

#define LDSM_X4(r, addr) \
    asm volatile("ldmatrix.sync.aligned.m8n8.x4.shared.b16 {%0,%1,%2,%3}, [%4];" \
        : "=r"((r)[0]), "=r"((r)[1]), "=r"((r)[2]), "=r"((r)[3]) : "r"(addr))

#define MMA16816(d, a, b) \
    asm volatile("mma.sync.aligned.m16n8k16.row.col.f32.f16.f16.f32 " \
        "{%0,%1,%2,%3},{%4,%5,%6,%7},{%8,%9},{%0,%1,%2,%3};" \
        : "+f"((d)[0]), "+f"((d)[1]), "+f"((d)[2]), "+f"((d)[3]) \
        : "r"((a)[0]), "r"((a)[1]), "r"((a)[2]), "r"((a)[3]), "r"((b)[0]), "r"((b)[1]))

// ---------------------------------------------------------------- scratch (stage-tiled, padded)
__device__ __half g_Hht[(size_t)NBLKS * KSTAGES * TILE_HALVES];   // 151 MB
__device__ __half g_WhTt[NCHUNKS * KSTAGES * TILE_HALVES];        // 1.2 MB
__device__ __half g_W1T[HID * 32];                                // W1^T [n=512][k=32]
__device__ float  g_b2p[PDP];

// ---------------------------------------------------------------- prep
__global__ void prep_kernel(const float* __restrict__ W2, const float* __restrict__ b2,
                            const float* __restrict__ W1) {
    int idx = blockIdx.x * blockDim.x + threadIdx.x;
    if (idx < PDP * HID) {
        int n = idx >> 9;        // padded param col 0..1023
        int k = idx & 511;
        int f = n >> 5, p = n & 31;
        float w = (p < PPF) ? W2[k * PD + f * PPF + p] : 0.0f;
        // stage-tiled: tile (nc = n>>7, kt = k>>6), row n&127, col k&63
        size_t a = (((size_t)(n >> 7) * KSTAGES + (k >> 6)) * 128 + (n & 127)) * 72 + (k & 63);
        g_WhTt[a] = __float2half_rn(w);
    }
    if (idx < HID * 32) {
        int n = idx >> 5, k = idx & 31;
        g_W1T[idx] = __float2half_rn(W1[k * HID + n]);
    }
    if (idx < PDP) {
        int f = idx >> 5, p = idx & 31;
        g_b2p[idx] = (p < PPF) ? b2[f * PPF + p] : 0.0f;
    }
}

// ---------------------------------------------------------------- stage 1: H = relu(id@W1+b1) via HMMA
__global__ __launch_bounds__(256) void gemm1_kernel(
    const float* __restrict__ x, const float* __restrict__ b1)
{
    extern __shared__ char smem[];
    uint32_t sb = smem_u32(smem);
    int tid = threadIdx.x;
    int wid = tid >> 5, lane = tid & 31;
    size_t rb = (size_t)blockIdx.x * BM;

#pragma unroll
    for (int j = 0; j < 8; j++) {
        int idx = tid + 256 * j;
        int row = idx >> 4, c = idx & 15;
        float4 v = __ldg((const float4*)x + (rb + row) * 16 + c);
        __half2 h2 = __floats2half2_rn(v.y, v.w);
        *(__half2*)(smem + G1_XA + row * G1_ROWB + c * 4) = h2;
    }
#pragma unroll
    for (int j = 0; j < 8; j++) {
        int idx = tid + 256 * j;
        int row = idx >> 2, q = idx & 3;
        *(float4*)(smem + G1_W1 + row * G1_ROWB + q * 16) =
            ((const float4*)(g_W1T + row * 32))[q];
    }
    __syncthreads();

    int warpRow = (wid & 3) * 32;
    int warpCol = (wid >> 2) * 64;
    int aRow = (lane & 15);
    int aKof = (lane >> 4) * 8;
    int bN   = (lane & 7) + ((lane >> 4) << 3);
    int bKof = ((lane >> 3) & 1) * 8;

    uint32_t ah[2][2][4];
#pragma unroll
    for (int k16 = 0; k16 < 2; k16++)
#pragma unroll
        for (int mt = 0; mt < 2; mt++) {
            uint32_t aoff = (uint32_t)((warpRow + mt * 16 + aRow) * G1_ROWB + (k16 * 16 + aKof) * 2);
            LDSM_X4(ah[k16][mt], sb + G1_XA + aoff);
        }

#pragma unroll
    for (int ch = 0; ch < 4; ch++) {
        float acc[2][8][4];
#pragma unroll
        for (int mt = 0; mt < 2; mt++)
#pragma unroll
            for (int nt = 0; nt < 8; nt++)
#pragma unroll
                for (int r = 0; r < 4; r++) acc[mt][nt][r] = 0.0f;

#pragma unroll
        for (int k16 = 0; k16 < 2; k16++) {
#pragma unroll
            for (int p = 0; p < 4; p++) {
                uint32_t boff = (uint32_t)((ch * 128 + warpCol + p * 16 + bN) * G1_ROWB + (k16 * 16 + bKof) * 2);
                uint32_t bh[4];
                LDSM_X4(bh, sb + G1_W1 + boff);
#pragma unroll
                for (int mt = 0; mt < 2; mt++) {
                    MMA16816(acc[mt][2 * p],     ah[k16][mt], bh);
                    MMA16816(acc[mt][2 * p + 1], ah[k16][mt], bh + 2);
                }
            }
        }

        // epilogue: bias + relu + fp16 store into stage-tiled layout
#pragma unroll
        for (int mt = 0; mt < 2; mt++) {
#pragma unroll
            for (int nt = 0; nt < 8; nt++) {
                int r = warpRow + mt * 16 + (lane >> 2);
                int c = ch * 128 + warpCol + nt * 8 + (lane & 3) * 2;
                float2 bb = *(const float2*)(b1 + c);
                __half2 h0 = __floats2half2_rn(fmaxf(acc[mt][nt][0] + bb.x, 0.f),
                                               fmaxf(acc[mt][nt][1] + bb.y, 0.f));
                __half2 h1 = __floats2half2_rn(fmaxf(acc[mt][nt][2] + bb.x, 0.f),
                                               fmaxf(acc[mt][nt][3] + bb.y, 0.f));
                size_t a0 = (((size_t)blockIdx.x * KSTAGES + (c >> 6)) * 128 + r) * 72 + (c & 63);
                *(__half2*)(g_Hht + a0)          = h0;
                *(__half2*)(g_Hht + a0 + 8 * 72) = h1;   // row r+8, same tile
            }
        }
    }
}

// ---------------------------------------------------------------- spline
__device__ __forceinline__ float expp(float x) {
    float r = 8.333333333e-3f;
    r = r * x + 4.166666667e-2f;
    r = r * x + 1.666666667e-1f;
    r = r * x + 0.5f;
    r = r * x + 1.0f;
    r = r * x + 1.0f;
    return r;
}
__device__ __forceinline__ float softplusf_fast(float v) {
    return fmaxf(v, 0.0f) + __logf(1.0f + __expf(-fabsf(v)));
}

__device__ __forceinline__ void rqs_spline(float xv, const float* __restrict__ p,
                                           float& y_out, float& lad_out)
{
    const float S = 0.044194173824159216f;  // 1/sqrt(512)
    bool inside = (xv >= -1.0f) && (xv <= 1.0f);
    float xc = fminf(fmaxf(xv, -1.0f), 1.0f);

    float vw[10], vh[10];
    float sw = 0.0f, sh = 0.0f;
#pragma unroll
    for (int i = 0; i < 10; i++) {
        vw[i] = expp(p[i] * S);
        vh[i] = expp(p[10 + i] * S);
        sw += vw[i];
        sh += vh[i];
    }
    float rw = __fdividef(0.99f, sw), rh = __fdividef(0.99f, sh);

    float cumw = 0.0f, cumh = 0.0f;
    float Lw = -1.0f, Lh = -1.0f;
    float icw = -1.0f, iw = 1.0f, ich = -1.0f, ih = 1.0f;
    int isel = 0;
#pragma unroll
    for (int i = 0; i < 10; i++) {
        cumw += 0.001f + vw[i] * rw;
        cumh += 0.001f + vh[i] * rh;
        float Rw = (i == 9) ? 1.0f : (2.0f * cumw - 1.0f);
        float Rh = (i == 9) ? 1.0f : (2.0f * cumh - 1.0f);
        if (xc >= Lw) {
            icw = Lw; iw = Rw - Lw;
            ich = Lh; ih = Rh - Lh;
            isel = i;
        }
        Lw = Rw; Lh = Rh;
    }
    float dk  = (isel > 0) ? (0.001f + softplusf_fast(p[19 + isel])) : 1.0f;
    float dk1 = (isel < 9) ? (0.001f + softplusf_fast(p[20 + isel])) : 1.0f;

    float riw = __fdividef(1.0f, iw);
    float theta = (xc - icw) * riw;
    float om = 1.0f - theta;
    float t1m = theta * om;
    float delta = ih * riw;
    float numer = ih * (delta * theta * theta + dk * t1m);
    float denom = delta + (dk + dk1 - 2.0f * delta) * t1m;
    float rden = __fdividef(1.0f, denom);
    float yv = ich + numer * rden;
    float dnum = delta * delta * (dk1 * theta * theta + 2.0f * delta * t1m + dk * om * om);
    float l = __logf(dnum * rden * rden);

    y_out = inside ? yv : xv;
    lad_out = inside ? l : 0.0f;
}

// ---------------------------------------------------------------- stage 2: HMMA GEMM (bulk-DMA staged) + spline
__device__ __forceinline__ void issue_stage(uint32_t sb, int buf, int blk, int kt, int nc)
{
    uint32_t mb = sb + SM_MBAR + buf * 8;
    MBARRIER_EXPECT_TX(mb, 2 * TILE_BYTES);
    BULK_LD(sb + buf * STAGE_BYTES + OFF_A,
            (const char*)g_Hht + ((size_t)blk * KSTAGES + kt) * TILE_BYTES,
            TILE_BYTES, mb);
    BULK_LD(sb + buf * STAGE_BYTES + OFF_B,
            (const char*)g_WhTt + ((size_t)nc * KSTAGES + kt) * TILE_BYTES,
            TILE_BYTES, mb);
}

__global__ __launch_bounds__(256, 2) void gemm2_mma_kernel(
    const float* __restrict__ x, float* __restrict__ out,
    float* __restrict__ lad_out, float* __restrict__ ot_out)
{
    extern __shared__ char smem[];
    uint32_t sb = smem_u32(smem);
    int tid = threadIdx.x;
    int wid = tid >> 5, lane = tid & 31;
    int blk = blockIdx.x;
    size_t rb = (size_t)blk * BM;

    int warpRow = (wid & 3) * 32;        // 4 warp-rows of 32
    int warpCol = (wid >> 2) * 64;       // 2 warp-cols of 64

    float* Cs   = (float*)(smem + SM_CS);
    float* ladR = (float*)(smem + SM_LAD);
    float* otR  = (float*)(smem + SM_OT);

    int aRow = (lane & 15);
    int aKof = (lane >> 4) * 8;
    int bN   = (lane & 7) + ((lane >> 4) << 3);
    int bKof = ((lane >> 3) & 1) * 8;

    float lad_acc = 0.0f, ot_acc = 0.0f;
    int srow = tid & 127;

    if (tid == 0) {
        MBARRIER_INIT(sb + SM_MBAR, 1);
        MBARRIER_INIT(sb + SM_MBAR + 8, 1);
    }
    __syncthreads();
    if (tid == 0) issue_stage(sb, 0, blk, 0, 0);   // prefetch chunk0 stage0 -> buf0
    int ph0 = 0, ph1 = 0;

#pragma unroll 1
    for (int nc = 0; nc < NCHUNKS; nc++) {
        float acc[2][8][4];
#pragma unroll
        for (int mt = 0; mt < 2; mt++)
#pragma unroll
            for (int nt = 0; nt < 8; nt++)
#pragma unroll
                for (int r = 0; r < 4; r++) acc[mt][nt][r] = 0.0f;

        // single-sync double-buffered pipeline, mbarrier-paced DMA
#pragma unroll 1
        for (int kt = 0; kt < KSTAGES; kt++) {
            int buf = kt & 1;
            if (buf == 0) { MBARRIER_WAIT_PARITY(sb + SM_MBAR,     ph0); ph0 ^= 1; }
            else          { MBARRIER_WAIT_PARITY(sb + SM_MBAR + 8, ph1); ph1 ^= 1; }
            __syncthreads();   // all warps past their reads of buf^1 (and past spline at kt=0)
            if (tid == 0) {
                if (kt + 1 < KSTAGES)       issue_stage(sb, buf ^ 1, blk, kt + 1, nc);
                else if (nc + 1 < NCHUNKS)  issue_stage(sb, 0,       blk, 0,      nc + 1);
            }

            uint32_t base = sb + buf * STAGE_BYTES;
#pragma unroll
            for (int k16 = 0; k16 < 4; k16++) {
                int ko = k16 * 16;
                uint32_t ah[2][4];
#pragma unroll
                for (int mt = 0; mt < 2; mt++) {
                    uint32_t aoff = (uint32_t)((warpRow + mt * 16 + aRow) * ROWB + (ko + aKof) * 2);
                    LDSM_X4(ah[mt], base + OFF_A + aoff);
                }
#pragma unroll
                for (int p = 0; p < 4; p++) {
                    uint32_t boff = (uint32_t)((warpCol + p * 16 + bN) * ROWB + (ko + bKof) * 2);
                    uint32_t bh[4];
                    LDSM_X4(bh, base + OFF_B + boff);
#pragma unroll
                    for (int mt = 0; mt < 2; mt++) {
                        MMA16816(acc[mt][2 * p],     ah[mt], bh);
                        MMA16816(acc[mt][2 * p + 1], ah[mt], bh + 2);
                    }
                }
            }
        }
        __syncthreads();   // all warps done reading buf1 before dump overwrites it

        // ---- dump accumulators (+ bias fold) into Cs (scalar: CSTRIDE odd) ----
#pragma unroll
        for (int nt = 0; nt < 8; nt++) {
            int c = warpCol + nt * 8 + (lane & 3) * 2;
            float2 bb = __ldg((const float2*)(g_b2p + nc * NT + c));
#pragma unroll
            for (int mt = 0; mt < 2; mt++) {
                int r = warpRow + mt * 16 + (lane >> 2);
                Cs[r * CSTRIDE + c]           = acc[mt][nt][0] + bb.x;
                Cs[r * CSTRIDE + c + 1]       = acc[mt][nt][1] + bb.y;
                Cs[(r + 8) * CSTRIDE + c]     = acc[mt][nt][2] + bb.x;
                Cs[(r + 8) * CSTRIDE + c + 1] = acc[mt][nt][3] + bb.y;
            }
        }
        __syncthreads();

        // ---- spline: 512 tasks, 2/thread, unrolled for ILP ----
#pragma unroll
        for (int t = 0; t < 2; t++) {
            int task = tid + 256 * t;
            int row = task & 127;
            int fl  = task >> 7;
            int fg  = nc * 4 + fl;
            const float* bp = Cs + row * CSTRIDE + fl * 32;
            float2 xp = *(const float2*)(x + (rb + row) * FEAT + 2 * fg);
            float y, lad;
            rqs_spline(xp.x, bp, y, lad);
            *(float2*)(out + (rb + row) * FEAT + 2 * fg) = make_float2(y, xp.y);
            lad_acc += lad;
            float d = xp.x - y;
            ot_acc += d * d;
        }
        // no post-spline sync: next chunk's kt=0 barrier orders spline reads
        // before the kt=1 DMA overwrites Cs (=buf1)
    }

    // ---- per-row reductions (rows covered by tid and tid+128) ----
    __syncthreads();
    if (tid < 128) { ladR[srow] = lad_acc; otR[srow] = ot_acc; }
    __syncthreads();
    if (tid >= 128) { ladR[srow] += lad_acc; otR[srow] += ot_acc; }
    __syncthreads();

    if (tid < BM) {
        lad_out[rb + tid] = ladR[tid];
        ot_out[rb + tid]  = otR[tid];
    }
}

// ---------------------------------------------------------------- launcher
extern "C" void kernel_launch(void* const* d_in, const int* in_sizes, int n_in,
                              void* d_out, int out_size)
{
    const float* x  = (const float*)d_in[0];
    const float* W1 = (const float*)d_in[1];
    const float* b1 = (const float*)d_in[2];
    const float* W2 = (const float*)d_in[3];
    const float* b2 = (const float*)d_in[4];

    float* out = (float*)d_out;
    float* lad = out + (size_t)BROWS * FEAT;
    float* ot  = lad + BROWS;

    cudaFuncSetAttribute(gemm1_kernel, cudaFuncAttributeMaxDynamicSharedMemorySize, G1_SMEM);
    cudaFuncSetAttribute(gemm2_mma_kernel, cudaFuncAttributeMaxDynamicSharedMemorySize, SMEM_TOTAL);

    prep_kernel<<<(PDP * HID + 255) / 256, 256>>>(W2, b2, W1);
    gemm1_kernel<<<BROWS / BM, 256, G1_SMEM>>>(x, b1);
    gemm2_mma_kernel<<<BROWS / BM, 256, SMEM_TOTAL>>>(x, out, lad, ot);
}

// round 15
// speedup vs baseline: 1.1850x; 1.0109x over previous
#include <cuda_runtime.h>
#include <cuda_fp16.h>
#include <math.h>
#include <stdint.h>

// ---------------------------------------------------------------- constants
#define BROWS  131072
#define FEAT   64
#define HID    512
#define NB     10
#define PPF    29
#define PD     928
#define PDP    1024

#define BM      128
#define NT      128            // N per chunk (4 features x 32 padded params)
#define KT      64             // K per stage
#define NCHUNKS (PDP/NT)       // 8
#define KSTAGES (HID/KT)       // 8
#define NBLKS   (BROWS/BM)     // 1024

// stage tile: 128 rows x 72 halves (144B, padding baked into GMEM layout)
#define ROWB   144
#define TILE_HALVES (128*72)       // 9216
#define TILE_BYTES  (128*ROWB)     // 18432
#define OFF_A  0
#define OFF_B  18432
#define STAGE_BYTES 36864
// Cs: SEPARATE fp16 region (no stage aliasing -> both bufs prefetchable in spline)
#define SM_CS   (2*STAGE_BYTES)          // 73728
#define CSTRIDE 134                       // halves; 67 words, odd -> spline conflict-free
#define CS_BYTES (BM*CSTRIDE*2)           // 34304
#define SM_LAD  (SM_CS + CS_BYTES)        // 108032
#define SM_OT   (SM_LAD + BM*4)
#define SM_MBAR (SM_OT + BM*4)            // 109056
#define SMEM_TOTAL (SM_MBAR + 16)         // 109072 -> 2 CTAs/SM

// gemm1 smem
#define G1_ROWB 80
#define G1_XA   0
#define G1_W1   10240
#define G1_SMEM 51200

// ---------------------------------------------------------------- asm helpers
__device__ __forceinline__ uint32_t smem_u32(const void* p) {
    uint32_t a;
    asm("{ .reg .u64 t; cvta.to.shared.u64 t, %1; cvt.u32.u64 %0, t; }" : "=r"(a) : "l"(p));
    return a;
}
#define MBARRIER_INIT(addr, cnt) \
    asm volatile("mbarrier.init.shared.b64 [%0], %1;" :: "r"(addr), "r"(cnt) : "memory")
#define MBARRIER_EXPECT_TX(addr, bytes) \
    asm volatile("mbarrier.arrive.expect_tx.shared.b64 _, [%0], %1;" :: "r"(addr), "r"(bytes) : "memory")
#define MBARRIER_WAIT_PARITY(addr, par) do { \
    uint32_t _m = (addr), _p = (par), _d; \
    asm volatile("{ .reg .pred p; mbarrier.try_wait.parity.acquire.cta.shared::cta.b64 p, [%1], %2; selp.b32 %0,1,0,p; }" \
        : "=r"(_d) : "r"(_m), "r"(_p) : "memory"); \
    if (!_d) { \
        asm volatile("{ .reg .pred P1;\nWL_%=:\nmbarrier.try_wait.parity.acquire.cta.shared::cta.b64 P1, [%0], %1, 0x989680;\n@P1 bra.uni WD_%=;\nbra.uni WL_%=;\nWD_%=:\n}" \
            :: "r"(_m), "r"(_p) : "memory"); \
    } } while (0)
#define BULK_LD(dst, src, sz, mb) \
    asm volatile("cp.async.bulk.shared::cluster.global.mbarrier::complete_tx::bytes [%0], [%1], %2, [%3];" \
        :: "r"(dst), "l"(src), "r"(sz), "r"(mb) : "memory")

#define LDSM_X4(r, addr) \
    asm volatile("ldmatrix.sync.aligned.m8n8.x4.shared.b16 {%0,%1,%2,%3}, [%4];" \
        : "=r"((r)[0]), "=r"((r)[1]), "=r"((r)[2]), "=r"((r)[3]) : "r"(addr))

#define MMA16816(d, a, b) \
    asm volatile("mma.sync.aligned.m16n8k16.row.col.f32.f16.f16.f32 " \
        "{%0,%1,%2,%3},{%4,%5,%6,%7},{%8,%9},{%0,%1,%2,%3};" \
        : "+f"((d)[0]), "+f"((d)[1]), "+f"((d)[2]), "+f"((d)[3]) \
        : "r"((a)[0]), "r"((a)[1]), "r"((a)[2]), "r"((a)[3]), "r"((b)[0]), "r"((b)[1]))

// ---------------------------------------------------------------- scratch (stage-tiled, padded)
__device__ __half g_Hht[(size_t)NBLKS * KSTAGES * TILE_HALVES];   // 151 MB
__device__ __half g_WhTt[NCHUNKS * KSTAGES * TILE_HALVES];        // 1.2 MB
__device__ __half g_W1T[HID * 32];                                // W1^T [n=512][k=32]
__device__ float  g_b2p[PDP];

// ---------------------------------------------------------------- prep
__global__ void prep_kernel(const float* __restrict__ W2, const float* __restrict__ b2,
                            const float* __restrict__ W1) {
    int idx = blockIdx.x * blockDim.x + threadIdx.x;
    if (idx < PDP * HID) {
        int n = idx >> 9;        // padded param col 0..1023
        int k = idx & 511;
        int f = n >> 5, p = n & 31;
        float w = (p < PPF) ? W2[k * PD + f * PPF + p] : 0.0f;
        size_t a = (((size_t)(n >> 7) * KSTAGES + (k >> 6)) * 128 + (n & 127)) * 72 + (k & 63);
        g_WhTt[a] = __float2half_rn(w);
    }
    if (idx < HID * 32) {
        int n = idx >> 5, k = idx & 31;
        g_W1T[idx] = __float2half_rn(W1[k * HID + n]);
    }
    if (idx < PDP) {
        int f = idx >> 5, p = idx & 31;
        g_b2p[idx] = (p < PPF) ? b2[f * PPF + p] : 0.0f;
    }
}

// ---------------------------------------------------------------- stage 1: H = relu(id@W1+b1) via HMMA
__global__ __launch_bounds__(256) void gemm1_kernel(
    const float* __restrict__ x, const float* __restrict__ b1)
{
    extern __shared__ char smem[];
    uint32_t sb = smem_u32(smem);
    int tid = threadIdx.x;
    int wid = tid >> 5, lane = tid & 31;
    size_t rb = (size_t)blockIdx.x * BM;

#pragma unroll
    for (int j = 0; j < 8; j++) {
        int idx = tid + 256 * j;
        int row = idx >> 4, c = idx & 15;
        float4 v = __ldg((const float4*)x + (rb + row) * 16 + c);
        __half2 h2 = __floats2half2_rn(v.y, v.w);
        *(__half2*)(smem + G1_XA + row * G1_ROWB + c * 4) = h2;
    }
#pragma unroll
    for (int j = 0; j < 8; j++) {
        int idx = tid + 256 * j;
        int row = idx >> 2, q = idx & 3;
        *(float4*)(smem + G1_W1 + row * G1_ROWB + q * 16) =
            ((const float4*)(g_W1T + row * 32))[q];
    }
    __syncthreads();

    int warpRow = (wid & 3) * 32;
    int warpCol = (wid >> 2) * 64;
    int aRow = (lane & 15);
    int aKof = (lane >> 4) * 8;
    int bN   = (lane & 7) + ((lane >> 4) << 3);
    int bKof = ((lane >> 3) & 1) * 8;

    uint32_t ah[2][2][4];
#pragma unroll
    for (int k16 = 0; k16 < 2; k16++)
#pragma unroll
        for (int mt = 0; mt < 2; mt++) {
            uint32_t aoff = (uint32_t)((warpRow + mt * 16 + aRow) * G1_ROWB + (k16 * 16 + aKof) * 2);
            LDSM_X4(ah[k16][mt], sb + G1_XA + aoff);
        }

#pragma unroll
    for (int ch = 0; ch < 4; ch++) {
        float acc[2][8][4];
#pragma unroll
        for (int mt = 0; mt < 2; mt++)
#pragma unroll
            for (int nt = 0; nt < 8; nt++)
#pragma unroll
                for (int r = 0; r < 4; r++) acc[mt][nt][r] = 0.0f;

#pragma unroll
        for (int k16 = 0; k16 < 2; k16++) {
#pragma unroll
            for (int p = 0; p < 4; p++) {
                uint32_t boff = (uint32_t)((ch * 128 + warpCol + p * 16 + bN) * G1_ROWB + (k16 * 16 + bKof) * 2);
                uint32_t bh[4];
                LDSM_X4(bh, sb + G1_W1 + boff);
#pragma unroll
                for (int mt = 0; mt < 2; mt++) {
                    MMA16816(acc[mt][2 * p],     ah[k16][mt], bh);
                    MMA16816(acc[mt][2 * p + 1], ah[k16][mt], bh + 2);
                }
            }
        }

        // epilogue: bias + relu + fp16 store into stage-tiled layout
#pragma unroll
        for (int mt = 0; mt < 2; mt++) {
#pragma unroll
            for (int nt = 0; nt < 8; nt++) {
                int r = warpRow + mt * 16 + (lane >> 2);
                int c = ch * 128 + warpCol + nt * 8 + (lane & 3) * 2;
                float2 bb = *(const float2*)(b1 + c);
                __half2 h0 = __floats2half2_rn(fmaxf(acc[mt][nt][0] + bb.x, 0.f),
                                               fmaxf(acc[mt][nt][1] + bb.y, 0.f));
                __half2 h1 = __floats2half2_rn(fmaxf(acc[mt][nt][2] + bb.x, 0.f),
                                               fmaxf(acc[mt][nt][3] + bb.y, 0.f));
                size_t a0 = (((size_t)blockIdx.x * KSTAGES + (c >> 6)) * 128 + r) * 72 + (c & 63);
                *(__half2*)(g_Hht + a0)          = h0;
                *(__half2*)(g_Hht + a0 + 8 * 72) = h1;   // row r+8, same tile
            }
        }
    }
}

// ---------------------------------------------------------------- spline
__device__ __forceinline__ float expp(float x) {
    float r = 8.333333333e-3f;
    r = r * x + 4.166666667e-2f;
    r = r * x + 1.666666667e-1f;
    r = r * x + 0.5f;
    r = r * x + 1.0f;
    r = r * x + 1.0f;
    return r;
}
__device__ __forceinline__ float softplusf_fast(float v) {
    return fmaxf(v, 0.0f) + __logf(1.0f + __expf(-fabsf(v)));
}

// p: fp16 params in smem (bias already folded)
__device__ __forceinline__ void rqs_spline(float xv, const __half* __restrict__ p,
                                           float& y_out, float& lad_out)
{
    const float S = 0.044194173824159216f;  // 1/sqrt(512)
    bool inside = (xv >= -1.0f) && (xv <= 1.0f);
    float xc = fminf(fmaxf(xv, -1.0f), 1.0f);

    float vw[10], vh[10];
    float sw = 0.0f, sh = 0.0f;
#pragma unroll
    for (int i = 0; i < 10; i++) {
        vw[i] = expp(__half2float(p[i]) * S);
        vh[i] = expp(__half2float(p[10 + i]) * S);
        sw += vw[i];
        sh += vh[i];
    }
    float rw = __fdividef(0.99f, sw), rh = __fdividef(0.99f, sh);

    float cumw = 0.0f, cumh = 0.0f;
    float Lw = -1.0f, Lh = -1.0f;
    float icw = -1.0f, iw = 1.0f, ich = -1.0f, ih = 1.0f;
    int isel = 0;
#pragma unroll
    for (int i = 0; i < 10; i++) {
        cumw += 0.001f + vw[i] * rw;
        cumh += 0.001f + vh[i] * rh;
        float Rw = (i == 9) ? 1.0f : (2.0f * cumw - 1.0f);
        float Rh = (i == 9) ? 1.0f : (2.0f * cumh - 1.0f);
        if (xc >= Lw) {
            icw = Lw; iw = Rw - Lw;
            ich = Lh; ih = Rh - Lh;
            isel = i;
        }
        Lw = Rw; Lh = Rh;
    }
    float dk  = (isel > 0) ? (0.001f + softplusf_fast(__half2float(p[19 + isel]))) : 1.0f;
    float dk1 = (isel < 9) ? (0.001f + softplusf_fast(__half2float(p[20 + isel]))) : 1.0f;

    float riw = __fdividef(1.0f, iw);
    float theta = (xc - icw) * riw;
    float om = 1.0f - theta;
    float t1m = theta * om;
    float delta = ih * riw;
    float numer = ih * (delta * theta * theta + dk * t1m);
    float denom = delta + (dk + dk1 - 2.0f * delta) * t1m;
    float rden = __fdividef(1.0f, denom);
    float yv = ich + numer * rden;
    float dnum = delta * delta * (dk1 * theta * theta + 2.0f * delta * t1m + dk * om * om);
    float l = __logf(dnum * rden * rden);

    y_out = inside ? yv : xv;
    lad_out = inside ? l : 0.0f;
}

// ---------------------------------------------------------------- stage 2: HMMA GEMM (bulk-DMA) + spline
__device__ __forceinline__ void issue_stage(uint32_t sb, int buf, int blk, int kt, int nc)
{
    uint32_t mb = sb + SM_MBAR + buf * 8;
    MBARRIER_EXPECT_TX(mb, 2 * TILE_BYTES);
    BULK_LD(sb + buf * STAGE_BYTES + OFF_A,
            (const char*)g_Hht + ((size_t)blk * KSTAGES + kt) * TILE_BYTES,
            TILE_BYTES, mb);
    BULK_LD(sb + buf * STAGE_BYTES + OFF_B,
            (const char*)g_WhTt + ((size_t)nc * KSTAGES + kt) * TILE_BYTES,
            TILE_BYTES, mb);
}

__global__ __launch_bounds__(256, 2) void gemm2_mma_kernel(
    const float* __restrict__ x, float* __restrict__ out,
    float* __restrict__ lad_out, float* __restrict__ ot_out)
{
    extern __shared__ char smem[];
    uint32_t sb = smem_u32(smem);
    int tid = threadIdx.x;
    int wid = tid >> 5, lane = tid & 31;
    int blk = blockIdx.x;
    size_t rb = (size_t)blk * BM;

    int warpRow = (wid & 3) * 32;        // 4 warp-rows of 32
    int warpCol = (wid >> 2) * 64;       // 2 warp-cols of 64

    __half*  CsH  = (__half*)(smem + SM_CS);
    __half2* CsH2 = (__half2*)(smem + SM_CS);
    float* ladR = (float*)(smem + SM_LAD);
    float* otR  = (float*)(smem + SM_OT);

    int aRow = (lane & 15);
    int aKof = (lane >> 4) * 8;
    int bN   = (lane & 7) + ((lane >> 4) << 3);
    int bKof = ((lane >> 3) & 1) * 8;

    float lad_acc = 0.0f, ot_acc = 0.0f;
    int srow = tid & 127;

    if (tid == 0) {
        MBARRIER_INIT(sb + SM_MBAR, 1);
        MBARRIER_INIT(sb + SM_MBAR + 8, 1);
    }
    __syncthreads();
    if (tid == 0) {                        // prefetch st0 AND st1 of chunk 0
        issue_stage(sb, 0, blk, 0, 0);
        issue_stage(sb, 1, blk, 1, 0);
    }
    int ph0 = 0, ph1 = 0;

#pragma unroll 1
    for (int nc = 0; nc < NCHUNKS; nc++) {
        float acc[2][8][4];
#pragma unroll
        for (int mt = 0; mt < 2; mt++)
#pragma unroll
            for (int nt = 0; nt < 8; nt++)
#pragma unroll
                for (int r = 0; r < 4; r++) acc[mt][nt][r] = 0.0f;

#pragma unroll 1
        for (int kt = 0; kt < KSTAGES; kt++) {
            int buf = kt & 1;
            if (buf == 0) { MBARRIER_WAIT_PARITY(sb + SM_MBAR,     ph0); ph0 ^= 1; }
            else          { MBARRIER_WAIT_PARITY(sb + SM_MBAR + 8, ph1); ph1 ^= 1; }
            __syncthreads();   // all warps done with the buffer the next issue targets
            if (tid == 0 && kt >= 1 && kt < KSTAGES - 1)
                issue_stage(sb, (kt + 1) & 1, blk, kt + 1, nc);

            uint32_t base = sb + buf * STAGE_BYTES;
#pragma unroll
            for (int k16 = 0; k16 < 4; k16++) {
                int ko = k16 * 16;
                uint32_t ah[2][4];
#pragma unroll
                for (int mt = 0; mt < 2; mt++) {
                    uint32_t aoff = (uint32_t)((warpRow + mt * 16 + aRow) * ROWB + (ko + aKof) * 2);
                    LDSM_X4(ah[mt], base + OFF_A + aoff);
                }
#pragma unroll
                for (int p = 0; p < 4; p++) {
                    uint32_t boff = (uint32_t)((warpCol + p * 16 + bN) * ROWB + (ko + bKof) * 2);
                    uint32_t bh[4];
                    LDSM_X4(bh, base + OFF_B + boff);
#pragma unroll
                    for (int mt = 0; mt < 2; mt++) {
                        MMA16816(acc[mt][2 * p],     ah[mt], bh);
                        MMA16816(acc[mt][2 * p + 1], ah[mt], bh + 2);
                    }
                }
            }
        }
        __syncthreads();   // both buffers fully consumed

        // prefetch BOTH stages of the next chunk; they fly under dump+spline
        if (tid == 0 && nc + 1 < NCHUNKS) {
            issue_stage(sb, 0, blk, 0, nc + 1);
            issue_stage(sb, 1, blk, 1, nc + 1);
        }

        // ---- dump accumulators (+ bias) into fp16 Cs via half2 stores ----
#pragma unroll
        for (int nt = 0; nt < 8; nt++) {
            int c = warpCol + nt * 8 + (lane & 3) * 2;
            float2 bb = __ldg((const float2*)(g_b2p + nc * NT + c));
#pragma unroll
            for (int mt = 0; mt < 2; mt++) {
                int r = warpRow + mt * 16 + (lane >> 2);
                CsH2[(r * CSTRIDE + c) >> 1] =
                    __floats2half2_rn(acc[mt][nt][0] + bb.x, acc[mt][nt][1] + bb.y);
                CsH2[((r + 8) * CSTRIDE + c) >> 1] =
                    __floats2half2_rn(acc[mt][nt][2] + bb.x, acc[mt][nt][3] + bb.y);
            }
        }
        __syncthreads();

        // ---- spline: 512 tasks, 2/thread, unrolled for ILP ----
#pragma unroll
        for (int t = 0; t < 2; t++) {
            int task = tid + 256 * t;
            int row = task & 127;
            int fl  = task >> 7;
            int fg  = nc * 4 + fl;
            const __half* bp = CsH + row * CSTRIDE + fl * 32;
            float2 xp = *(const float2*)(x + (rb + row) * FEAT + 2 * fg);
            float y, lad;
            rqs_spline(xp.x, bp, y, lad);
            *(float2*)(out + (rb + row) * FEAT + 2 * fg) = make_float2(y, xp.y);
            lad_acc += lad;
            float d = xp.x - y;
            ot_acc += d * d;
        }
        // no trailing sync: Cs is private to dump/spline phases; next chunk's
        // kt=0 sync orders spline completion before any Cs rewrite
    }

    // ---- per-row reductions (rows covered by tid and tid+128) ----
    __syncthreads();
    if (tid < 128) { ladR[srow] = lad_acc; otR[srow] = ot_acc; }
    __syncthreads();
    if (tid >= 128) { ladR[srow] += lad_acc; otR[srow] += ot_acc; }
    __syncthreads();

    if (tid < BM) {
        lad_out[rb + tid] = ladR[tid];
        ot_out[rb + tid]  = otR[tid];
    }
}

// ---------------------------------------------------------------- launcher
extern "C" void kernel_launch(void* const* d_in, const int* in_sizes, int n_in,
                              void* d_out, int out_size)
{
    const float* x  = (const float*)d_in[0];
    const float* W1 = (const float*)d_in[1];
    const float* b1 = (const float*)d_in[2];
    const float* W2 = (const float*)d_in[3];
    const float* b2 = (const float*)d_in[4];

    float* out = (float*)d_out;
    float* lad = out + (size_t)BROWS * FEAT;
    float* ot  = lad + BROWS;

    cudaFuncSetAttribute(gemm1_kernel, cudaFuncAttributeMaxDynamicSharedMemorySize, G1_SMEM);
    cudaFuncSetAttribute(gemm2_mma_kernel, cudaFuncAttributeMaxDynamicSharedMemorySize, SMEM_TOTAL);

    prep_kernel<<<(PDP * HID + 255) / 256, 256>>>(W2, b2, W1);
    gemm1_kernel<<<BROWS / BM, 256, G1_SMEM>>>(x, b1);
    gemm2_mma_kernel<<<BROWS / BM, 256, SMEM_TOTAL>>>(x, out, lad, ot);
}